// round 3
// baseline (speedup 1.0000x reference)
#include <cuda_runtime.h>
#include <cstddef>

#define B 512
#define S 2048
#define V 29
#define H 128
#define CH 32                 // x prefetch chunk (steps)
#define NC (S / CH)           // 64 chunks
#define CHW (CH * V)          // 928 floats per chunk

typedef unsigned long long ull;

__device__ __forceinline__ void fma2(ull& d, ull a, ull b) {
    asm("fma.rn.f32x2 %0, %1, %2, %0;" : "+l"(d) : "l"(a), "l"(b));
}

__device__ __forceinline__ float sum2(ull u) {
    float lo = __uint_as_float((unsigned)(u & 0xffffffffull));
    float hi = __uint_as_float((unsigned)(u >> 32));
    return lo + hi;
}

__device__ __forceinline__ float fast_tanh(float x) {
    // tanh(x) = 1 - 2/(e^{2x}+1); MUFU.EX2 based, ~1e-7 per-step error.
    float e = exp2f(x * 2.885390081777927f); // 2/ln2
    return 1.0f - __fdividef(2.0f, e + 1.0f);
}

__global__ __launch_bounds__(128, 3)
void rnn_kernel(const float* __restrict__ x,
                const float* __restrict__ We_ih,
                const float* __restrict__ We_hh,
                const float* __restrict__ be_ih,
                const float* __restrict__ be_hh,
                const float* __restrict__ Wd_ih,
                const float* __restrict__ Wd_hh,
                const float* __restrict__ bd_ih,
                const float* __restrict__ bd_hh,
                float* __restrict__ out)
{
    const int b = blockIdx.x;
    const int i = threadIdx.x;

    __shared__ __align__(16) ull   sW2[15 * 128];     // input-proj pairs, [p][i]
    __shared__ __align__(16) float hb[2][H];          // h double buffer
    __shared__ __align__(16) float sx[2][CH][32];     // x ring, padded stride 32

    // ---- init ----
    // We_hh row i -> registers as packed f32x2 pairs (64 ull = 128 regs)
    ull w2[H / 2];
    {
        const ulonglong2* wr = (const ulonglong2*)(We_hh + (size_t)i * H);
        #pragma unroll
        for (int q = 0; q < H / 4; q++) {
            ulonglong2 v = wr[q];
            w2[2 * q]     = v.x;
            w2[2 * q + 1] = v.y;
        }
    }
    // input-proj weight pairs: sW2[p][i] = pack(We_ih[i][2p], We_ih[i][2p+1] or 0)
    {
        const float* wi = We_ih + (size_t)i * V;
        #pragma unroll
        for (int p = 0; p < 15; p++) {
            float lo = wi[2 * p];
            float hi = (2 * p + 1 < V) ? wi[2 * p + 1] : 0.0f;
            ull u = ((ull)__float_as_uint(hi) << 32) | (ull)__float_as_uint(lo);
            sW2[p * 128 + i] = u;
        }
    }
    const float bias = be_ih[i] + be_hh[i];

    // zero x ring (elements >= V stay 0 forever) and h
    #pragma unroll
    for (int r = 0; r < 16; r++)
        ((float*)sx)[i + 128 * r] = 0.0f;
    hb[0][i] = 0.0f;

    const float* xrow = x + (size_t)b * S * V;

    // synchronous load of chunk 0
    {
        float tmp[8];
        #pragma unroll
        for (int r = 0; r < 8; r++) {
            int idx = i + 128 * r;
            tmp[r] = (idx < CHW) ? __ldg(xrow + idx) : 0.0f;
        }
        __syncthreads();   // sW2 / sx-zero visible
        #pragma unroll
        for (int r = 0; r < 8; r++) {
            int idx = i + 128 * r;
            if (idx < CHW) sx[0][idx / V][idx % V] = tmp[r];
        }
    }
    __syncthreads();

    float* hr = hb[0];
    float* hw = hb[1];
    float  lbuf[8];

    #pragma unroll 1
    for (int c = 0; c < NC; c++) {
        const int haveNext = (c + 1 < NC);
        // issue LDGs for chunk c+1 now; STS deferred to mid-chunk
        #pragma unroll
        for (int r = 0; r < 8; r++) {
            int idx = i + 128 * r;
            lbuf[r] = 0.0f;
            if (haveNext && idx < CHW)
                lbuf[r] = __ldg(xrow + (size_t)(c + 1) * CHW + idx);
        }
        const float* xc = &sx[c & 1][0][0];

        #pragma unroll 1
        for (int tl = 0; tl < CH; tl++) {
            const float* xs = xc + tl * 32;
            ull a0 = 0, a1 = 0, a2 = 0, a3 = 0;
            // input projection: 15 packed FMAs
            #pragma unroll
            for (int p = 0; p < 15; p++) {
                ull xp = *(const ull*)(xs + 2 * p);         // broadcast LDS.64
                ull wv = sW2[p * 128 + i];
                if ((p & 3) == 0)      fma2(a0, wv, xp);
                else if ((p & 3) == 1) fma2(a1, wv, xp);
                else if ((p & 3) == 2) fma2(a2, wv, xp);
                else                   fma2(a3, wv, xp);
            }
            // recurrence: 64 packed FMAs, h via broadcast LDS.128
            const ulonglong2* hp = (const ulonglong2*)hr;
            #pragma unroll
            for (int j = 0; j < H / 4; j++) {
                ulonglong2 hv = hp[j];
                fma2(a0, w2[2 * j],     hv.x);
                fma2(a1, w2[2 * j + 1], hv.y);
            }
            float s = bias + ((sum2(a0) + sum2(a1)) + (sum2(a2) + sum2(a3)));
            float hn = fast_tanh(s);
            hw[i] = hn;
            if (tl == 15 && haveNext) {   // mid-chunk: LDG long landed
                #pragma unroll
                for (int r = 0; r < 8; r++) {
                    int idx = i + 128 * r;
                    if (idx < CHW) sx[(c + 1) & 1][idx / V][idx % V] = lbuf[r];
                }
            }
            __syncthreads();
            float* t = hr; hr = hw; hw = t;
        }
    }
    // final hidden state is in hr

    // ---- fused decoder: warp 0 handles this batch row ----
    if (i < 32) {
        const int lane = i;
        const bool act = (lane < V);
        float wd[V];
        float din = 0.0f;
        #pragma unroll
        for (int k = 0; k < V; k++) wd[k] = 0.0f;
        if (act) {
            din = bd_ih[lane] + bd_hh[lane];
            const float* wr = Wd_ih + (size_t)lane * H;
            float d0 = 0.f, d1 = 0.f, d2 = 0.f, d3 = 0.f;
            #pragma unroll
            for (int j = 0; j < H; j += 4) {
                d0 = fmaf(wr[j + 0], hr[j + 0], d0);
                d1 = fmaf(wr[j + 1], hr[j + 1], d1);
                d2 = fmaf(wr[j + 2], hr[j + 2], d2);
                d3 = fmaf(wr[j + 3], hr[j + 3], d3);
            }
            din += (d0 + d1) + (d2 + d3);
            #pragma unroll
            for (int k = 0; k < V; k++)
                wd[k] = Wd_hh[(size_t)lane * V + k];
        }

        float h = 0.0f;
        float* orow = out + (size_t)b * S * V;
        #pragma unroll 1
        for (int t = 0; t < S; t++) {
            float a0 = din, a1 = 0.f, a2 = 0.f, a3 = 0.f;
            #pragma unroll
            for (int k = 0; k < V; k++) {
                float hk = __shfl_sync(0xffffffffu, h, k);
                if ((k & 3) == 0)      a0 = fmaf(wd[k], hk, a0);
                else if ((k & 3) == 1) a1 = fmaf(wd[k], hk, a1);
                else if ((k & 3) == 2) a2 = fmaf(wd[k], hk, a2);
                else                   a3 = fmaf(wd[k], hk, a3);
            }
            h = fast_tanh((a0 + a1) + (a2 + a3));
            if (act) orow[(size_t)t * V + lane] = h;
        }
    }
}

extern "C" void kernel_launch(void* const* d_in, const int* in_sizes, int n_in,
                              void* d_out, int out_size)
{
    const float* x     = (const float*)d_in[0];
    const float* We_ih = (const float*)d_in[1];
    const float* We_hh = (const float*)d_in[2];
    const float* be_ih = (const float*)d_in[3];
    const float* be_hh = (const float*)d_in[4];
    const float* Wd_ih = (const float*)d_in[5];
    const float* Wd_hh = (const float*)d_in[6];
    const float* bd_ih = (const float*)d_in[7];
    const float* bd_hh = (const float*)d_in[8];
    float* out = (float*)d_out;

    rnn_kernel<<<B, 128>>>(x, We_ih, We_hh, be_ih, be_hh,
                           Wd_ih, Wd_hh, bd_ih, bd_hh, out);
}

// round 4
// speedup vs baseline: 2.1662x; 2.1662x over previous
#include <cuda_runtime.h>
#include <cstddef>

#define B 512
#define S 2048
#define V 29
#define H 128
#define RPC 4                 // rows per CTA
#define NCTA (B / RPC)        // 128
#define CH 16                 // x prefetch chunk (steps)
#define NC (S / CH)           // 128 chunks
#define CHW (CH * V * RPC)    // 1856 floats per chunk (all 4 rows)
#define PERROW (CH * V)       // 464

__device__ __forceinline__ float fast_tanh(float x) {
    // tanh(x) = 1 - 2/(e^{2x}+1); MUFU.EX2-based, ~1e-7 per-step error.
    float e = exp2f(x * 2.885390081777927f); // 2/ln2
    return 1.0f - __fdividef(2.0f, e + 1.0f);
}

__global__ __launch_bounds__(256, 1)
void rnn_kernel(const float* __restrict__ x,
                const float* __restrict__ We_ih,
                const float* __restrict__ We_hh,
                const float* __restrict__ be_ih,
                const float* __restrict__ be_hh,
                const float* __restrict__ Wd_ih,
                const float* __restrict__ Wd_hh,
                const float* __restrict__ bd_ih,
                const float* __restrict__ bd_hh,
                float* __restrict__ out)
{
    const int c = blockIdx.x;
    const int t = threadIdx.x;
    const int i = t & 127;        // h element index
    const int p = t >> 7;         // 0 -> rows {0,1}, 1 -> rows {2,3}

    __shared__ __align__(16) float hb[2][RPC][H];        // h ping-pong
    __shared__ __align__(16) float sx[2][RPC][CH][32];   // x ring, stride-32 pad

    // ---- weights to registers (shared across the 2 batch rows) ----
    float w[H];
    {
        const float4* wr = (const float4*)(We_hh + (size_t)i * H);
        #pragma unroll
        for (int j = 0; j < H / 4; j++) {
            float4 v = wr[j];
            w[4 * j + 0] = v.x; w[4 * j + 1] = v.y;
            w[4 * j + 2] = v.z; w[4 * j + 3] = v.w;
        }
    }
    float wih[32];
    {
        const float* q = We_ih + (size_t)i * V;
        #pragma unroll
        for (int k = 0; k < 32; k++) wih[k] = (k < V) ? q[k] : 0.0f;
    }
    const float bias = be_ih[i] + be_hh[i];

    // zero x ring (pads stay 0) and init h
    {
        float* sp = &sx[0][0][0][0];
        #pragma unroll
        for (int r = 0; r < (2 * RPC * CH * 32) / 256; r++)
            sp[t + 256 * r] = 0.0f;
    }
    if (t < 2 * RPC * H / 2) { // 256 threads cover 2*4*128=1024? no: do loop
    }
    #pragma unroll
    for (int r = 0; r < (2 * RPC * H) / 256; r++)
        (&hb[0][0][0])[t + 256 * r] = 0.0f;

    const float* xblk = x + (size_t)(RPC * c) * S * V;   // rows 4c..4c+3

    // ---- load chunk 0 synchronously ----
    {
        float tmp[8];
        int   row[8], st[8], kk[8];
        #pragma unroll
        for (int r = 0; r < 8; r++) {
            int idx = t + 256 * r;
            tmp[r] = 0.0f; row[r] = 0; st[r] = 0; kk[r] = 0;
            if (idx < CHW) {
                int rr  = idx / PERROW;
                int off = idx - rr * PERROW;
                row[r] = rr; st[r] = off / V; kk[r] = off - (off / V) * V;
                tmp[r] = __ldg(xblk + (size_t)rr * S * V + off);
            }
        }
        __syncthreads();
        #pragma unroll
        for (int r = 0; r < 8; r++) {
            int idx = t + 256 * r;
            if (idx < CHW) sx[0][row[r]][st[r]][kk[r]] = tmp[r];
        }
    }
    __syncthreads();

    int cur = 0;
    float lbuf[8];

    #pragma unroll 1
    for (int ch = 0; ch < NC; ch++) {
        const int haveNext = (ch + 1 < NC);
        // issue LDGs for next chunk
        #pragma unroll
        for (int r = 0; r < 8; r++) {
            int idx = t + 256 * r;
            lbuf[r] = 0.0f;
            if (haveNext && idx < CHW) {
                int rr  = idx / PERROW;
                int off = idx - rr * PERROW;
                lbuf[r] = __ldg(xblk + (size_t)rr * S * V + (size_t)(ch + 1) * PERROW + off);
            }
        }

        #pragma unroll 1
        for (int tl = 0; tl < CH; tl++) {
            const float4* x0 = (const float4*)&sx[ch & 1][2 * p + 0][tl][0];
            const float4* x1 = (const float4*)&sx[ch & 1][2 * p + 1][tl][0];
            const float4* h0 = (const float4*)&hb[cur][2 * p + 0][0];
            const float4* h1 = (const float4*)&hb[cur][2 * p + 1][0];

            float a0 = bias, a1 = 0.f, b0 = bias, b1 = 0.f;

            // input projection (32 padded, wih pad = 0)
            #pragma unroll
            for (int j = 0; j < 8; j++) {
                float4 v0 = x0[j], v1 = x1[j];
                a0 = fmaf(wih[4 * j + 0], v0.x, a0);
                b0 = fmaf(wih[4 * j + 0], v1.x, b0);
                a1 = fmaf(wih[4 * j + 1], v0.y, a1);
                b1 = fmaf(wih[4 * j + 1], v1.y, b1);
                a0 = fmaf(wih[4 * j + 2], v0.z, a0);
                b0 = fmaf(wih[4 * j + 2], v1.z, b0);
                a1 = fmaf(wih[4 * j + 3], v0.w, a1);
                b1 = fmaf(wih[4 * j + 3], v1.w, b1);
            }
            // recurrence
            #pragma unroll
            for (int j = 0; j < 32; j++) {
                float4 v0 = h0[j], v1 = h1[j];
                a0 = fmaf(w[4 * j + 0], v0.x, a0);
                b0 = fmaf(w[4 * j + 0], v1.x, b0);
                a1 = fmaf(w[4 * j + 1], v0.y, a1);
                b1 = fmaf(w[4 * j + 1], v1.y, b1);
                a0 = fmaf(w[4 * j + 2], v0.z, a0);
                b0 = fmaf(w[4 * j + 2], v1.z, b0);
                a1 = fmaf(w[4 * j + 3], v0.w, a1);
                b1 = fmaf(w[4 * j + 3], v1.w, b1);
            }
            float hA = fast_tanh(a0 + a1);
            float hB = fast_tanh(b0 + b1);
            hb[cur ^ 1][2 * p + 0][i] = hA;
            hb[cur ^ 1][2 * p + 1][i] = hB;

            if (tl == CH / 2 && haveNext) {
                #pragma unroll
                for (int r = 0; r < 8; r++) {
                    int idx = t + 256 * r;
                    if (idx < CHW) {
                        int rr  = idx / PERROW;
                        int off = idx - rr * PERROW;
                        int stp = off / V;
                        sx[(ch + 1) & 1][rr][stp][off - stp * V] = lbuf[r];
                    }
                }
            }
            __syncthreads();
            cur ^= 1;
        }
    }
    // final hidden states in hb[cur][r][*]

    // ---- fused decoder: warp r decodes row 4c+r ----
    const int wid  = t >> 5;
    const int lane = t & 31;
    if (wid < RPC) {
        const int  r   = wid;
        const bool act = (lane < V);
        const float* hf = hb[cur][r];

        float wd[V];
        float din = 0.0f;
        #pragma unroll
        for (int k = 0; k < V; k++) wd[k] = 0.0f;
        if (act) {
            din = bd_ih[lane] + bd_hh[lane];
            const float* wr = Wd_ih + (size_t)lane * H;
            float d0 = 0.f, d1 = 0.f, d2 = 0.f, d3 = 0.f;
            #pragma unroll
            for (int j = 0; j < H; j += 4) {
                d0 = fmaf(wr[j + 0], hf[j + 0], d0);
                d1 = fmaf(wr[j + 1], hf[j + 1], d1);
                d2 = fmaf(wr[j + 2], hf[j + 2], d2);
                d3 = fmaf(wr[j + 3], hf[j + 3], d3);
            }
            din += (d0 + d1) + (d2 + d3);
            #pragma unroll
            for (int k = 0; k < V; k++)
                wd[k] = Wd_hh[(size_t)lane * V + k];
        }

        float h = 0.0f;
        float* orow = out + (size_t)(RPC * c + r) * S * V;
        #pragma unroll 1
        for (int tt = 0; tt < S; tt++) {
            float a0 = din, a1 = 0.f, a2 = 0.f, a3 = 0.f;
            #pragma unroll
            for (int k = 0; k < V; k++) {
                float hk = __shfl_sync(0xffffffffu, h, k);
                if ((k & 3) == 0)      a0 = fmaf(wd[k], hk, a0);
                else if ((k & 3) == 1) a1 = fmaf(wd[k], hk, a1);
                else if ((k & 3) == 2) a2 = fmaf(wd[k], hk, a2);
                else                   a3 = fmaf(wd[k], hk, a3);
            }
            h = fast_tanh((a0 + a1) + (a2 + a3));
            if (act) orow[(size_t)tt * V + lane] = h;
        }
    }
}

extern "C" void kernel_launch(void* const* d_in, const int* in_sizes, int n_in,
                              void* d_out, int out_size)
{
    const float* x     = (const float*)d_in[0];
    const float* We_ih = (const float*)d_in[1];
    const float* We_hh = (const float*)d_in[2];
    const float* be_ih = (const float*)d_in[3];
    const float* be_hh = (const float*)d_in[4];
    const float* Wd_ih = (const float*)d_in[5];
    const float* Wd_hh = (const float*)d_in[6];
    const float* bd_ih = (const float*)d_in[7];
    const float* bd_hh = (const float*)d_in[8];
    float* out = (float*)d_out;

    rnn_kernel<<<NCTA, 256>>>(x, We_ih, We_hh, be_ih, be_hh,
                              Wd_ih, Wd_hh, bd_ih, bd_hh, out);
}

// round 5
// speedup vs baseline: 2.2114x; 1.0209x over previous
#include <cuda_runtime.h>
#include <cstddef>

#define B 512
#define S 2048
#define V 29
#define H 128
#define RPC 4                  // rows per CTA
#define NCTA (B / RPC)         // 128
#define CH 16                  // x prefetch chunk (steps)
#define NC (S / CH)            // 128 chunks
#define PERROW (CH * V)        // 464 floats per row per chunk
#define GRPW (2 * PERROW)      // 928 floats per row-group per chunk

typedef unsigned long long ull;

__device__ __forceinline__ void fma2(ull& d, ull a, ull b) {
    asm("fma.rn.f32x2 %0, %1, %2, %0;" : "+l"(d) : "l"(a), "l"(b));
}
__device__ __forceinline__ ull pack2(float lo, float hi) {
    ull u;
    asm("mov.b64 %0, {%1, %2};" : "=l"(u) : "f"(lo), "f"(hi));
    return u;
}
__device__ __forceinline__ float sum2(ull u) {
    float lo = __uint_as_float((unsigned)(u & 0xffffffffull));
    float hi = __uint_as_float((unsigned)(u >> 32));
    return lo + hi;
}
__device__ __forceinline__ float fast_tanh(float x) {
    float e = exp2f(x * 2.885390081777927f); // 2/ln2
    return 1.0f - __fdividef(2.0f, e + 1.0f);
}

__global__ __launch_bounds__(256, 1)
void rnn_kernel(const float* __restrict__ x,
                const float* __restrict__ We_ih,
                const float* __restrict__ We_hh,
                const float* __restrict__ be_ih,
                const float* __restrict__ be_hh,
                const float* __restrict__ Wd_ih,
                const float* __restrict__ Wd_hh,
                const float* __restrict__ bd_ih,
                const float* __restrict__ bd_hh,
                float* __restrict__ out)
{
    const int c  = blockIdx.x;
    const int t  = threadIdx.x;
    const int i  = t & 127;       // h element index
    const int p  = t >> 7;        // row group: p=0 -> rows {0,1}, p=1 -> {2,3}
    const int tl = t & 127;       // tid within group

    __shared__ __align__(16) float hb[2][RPC][H];
    __shared__ __align__(16) float sx[2][RPC][CH][32];   // stride-32 pad, cols>=V stay 0

    // ---- We_hh row i -> packed f32x2 register pairs ----
    ull w2[H / 2];
    {
        const ulonglong2* wr = (const ulonglong2*)(We_hh + (size_t)i * H);
        #pragma unroll
        for (int q = 0; q < H / 4; q++) {
            ulonglong2 v = wr[q];
            w2[2 * q] = v.x; w2[2 * q + 1] = v.y;
        }
    }
    // ---- We_ih row i -> 16 packed pairs (padded) ----
    ull wih2[16];
    {
        const float* q = We_ih + (size_t)i * V;
        #pragma unroll
        for (int k = 0; k < 16; k++) {
            float lo = (2 * k     < V) ? q[2 * k]     : 0.0f;
            float hi = (2 * k + 1 < V) ? q[2 * k + 1] : 0.0f;
            wih2[k] = pack2(lo, hi);
        }
    }
    const float bias = be_ih[i] + be_hh[i];

    // zero x ring & h (once)
    {
        float* sp = &sx[0][0][0][0];
        #pragma unroll
        for (int r = 0; r < (2 * RPC * CH * 32) / 256; r++) sp[t + 256 * r] = 0.0f;
    }
    #pragma unroll
    for (int r = 0; r < (2 * RPC * H) / 256; r++) (&hb[0][0][0])[t + 256 * r] = 0.0f;

    const float* xgrp = x + (size_t)(RPC * c + 2 * p) * S * V;  // this group's 2 rows

    // ---- chunk 0, group-local ----
    {
        float tmp[8]; int rr[8], st[8], kk[8];
        #pragma unroll
        for (int r = 0; r < 8; r++) {
            int idx = tl + 128 * r;
            tmp[r] = 0.0f; rr[r] = 0; st[r] = 0; kk[r] = 0;
            if (idx < GRPW) {
                int g = idx / PERROW, off = idx - g * PERROW;
                rr[r] = g; st[r] = off / V; kk[r] = off - (off / V) * V;
                tmp[r] = __ldg(xgrp + (size_t)g * S * V + off);
            }
        }
        __syncthreads();
        #pragma unroll
        for (int r = 0; r < 8; r++) {
            int idx = tl + 128 * r;
            if (idx < GRPW) sx[0][2 * p + rr[r]][st[r]][kk[r]] = tmp[r];
        }
    }
    __syncthreads();

    int cur = 0;
    float lbuf[8];

    #pragma unroll 1
    for (int ch = 0; ch < NC; ch++) {
        const int haveNext = (ch + 1 < NC);
        #pragma unroll
        for (int r = 0; r < 8; r++) {
            int idx = tl + 128 * r;
            lbuf[r] = 0.0f;
            if (haveNext && idx < GRPW) {
                int g = idx / PERROW, off = idx - g * PERROW;
                lbuf[r] = __ldg(xgrp + (size_t)g * S * V + (size_t)(ch + 1) * PERROW + off);
            }
        }

        #pragma unroll 1
        for (int tlp = 0; tlp < CH; tlp++) {
            const ulonglong2* X0 = (const ulonglong2*)&sx[ch & 1][2 * p + 0][tlp][0];
            const ulonglong2* X1 = (const ulonglong2*)&sx[ch & 1][2 * p + 1][tlp][0];
            const ulonglong2* H0 = (const ulonglong2*)&hb[cur][2 * p + 0][0];
            const ulonglong2* H1 = (const ulonglong2*)&hb[cur][2 * p + 1][0];

            ull a0 = 0, a1 = 0, b0 = 0, b1 = 0;

            #pragma unroll
            for (int j = 0; j < 8; j++) {              // input proj: 16 pairs/row
                ulonglong2 v0 = X0[j], v1 = X1[j];
                fma2(a0, wih2[2 * j],     v0.x);
                fma2(b0, wih2[2 * j],     v1.x);
                fma2(a1, wih2[2 * j + 1], v0.y);
                fma2(b1, wih2[2 * j + 1], v1.y);
            }
            #pragma unroll
            for (int j = 0; j < 32; j++) {             // recurrence: 64 pairs/row
                ulonglong2 v0 = H0[j], v1 = H1[j];
                fma2(a0, w2[2 * j],     v0.x);
                fma2(b0, w2[2 * j],     v1.x);
                fma2(a1, w2[2 * j + 1], v0.y);
                fma2(b1, w2[2 * j + 1], v1.y);
            }
            float hA = fast_tanh(bias + (sum2(a0) + sum2(a1)));
            float hB = fast_tanh(bias + (sum2(b0) + sum2(b1)));
            hb[cur ^ 1][2 * p + 0][i] = hA;
            hb[cur ^ 1][2 * p + 1][i] = hB;

            if (tlp == CH / 2 && haveNext) {           // deferred STS of next chunk
                #pragma unroll
                for (int r = 0; r < 8; r++) {
                    int idx = tl + 128 * r;
                    if (idx < GRPW) {
                        int g = idx / PERROW, off = idx - g * PERROW;
                        int st = off / V;
                        sx[(ch + 1) & 1][2 * p + g][st][off - st * V] = lbuf[r];
                    }
                }
            }
            // group-local named barrier: rows are independent across groups
            asm volatile("bar.sync %0, 128;" :: "r"(1 + p) : "memory");
            cur ^= 1;
        }
    }
    __syncthreads();   // decoder warps read the other group's h

    // ---- fused decoder: warp r decodes row RPC*c + r; fixed-point early exit ----
    const int wid  = t >> 5;
    const int lane = t & 31;
    if (wid < RPC) {
        const int  r   = wid;
        const bool act = (lane < V);
        const float* hf = hb[cur][r];

        float wd[V];
        float din = 0.0f;
        #pragma unroll
        for (int k = 0; k < V; k++) wd[k] = 0.0f;
        if (act) {
            din = bd_ih[lane] + bd_hh[lane];
            const float* wr = Wd_ih + (size_t)lane * H;
            float d0 = 0.f, d1 = 0.f, d2 = 0.f, d3 = 0.f;
            #pragma unroll
            for (int j = 0; j < H; j += 4) {
                d0 = fmaf(wr[j + 0], hf[j + 0], d0);
                d1 = fmaf(wr[j + 1], hf[j + 1], d1);
                d2 = fmaf(wr[j + 2], hf[j + 2], d2);
                d3 = fmaf(wr[j + 3], hf[j + 3], d3);
            }
            din += (d0 + d1) + (d2 + d3);
            #pragma unroll
            for (int k = 0; k < V; k++)
                wd[k] = Wd_hh[(size_t)lane * V + k];
        }

        float h = 0.0f;
        float* orow = out + (size_t)(RPC * c + r) * S * V;
        #pragma unroll 1
        for (int tt = 0; tt < S; tt++) {
            float a0 = din, a1 = 0.f, a2 = 0.f, a3 = 0.f;
            #pragma unroll
            for (int k = 0; k < V; k++) {
                float hk = __shfl_sync(0xffffffffu, h, k);
                if ((k & 3) == 0)      a0 = fmaf(wd[k], hk, a0);
                else if ((k & 3) == 1) a1 = fmaf(wd[k], hk, a1);
                else if ((k & 3) == 2) a2 = fmaf(wd[k], hk, a2);
                else                   a3 = fmaf(wd[k], hk, a3);
            }
            float hn = fast_tanh((a0 + a1) + (a2 + a3));
            if (act) orow[(size_t)tt * V + lane] = hn;
            // bitwise fixed point -> all later steps identical
            bool same = (__float_as_int(hn) == __float_as_int(h));
            h = hn;
            if (__all_sync(0xffffffffu, same)) {
                if (act)
                    for (int t2 = tt + 1; t2 < S; t2++)
                        orow[(size_t)t2 * V + lane] = h;
                break;
            }
        }
    }
}

extern "C" void kernel_launch(void* const* d_in, const int* in_sizes, int n_in,
                              void* d_out, int out_size)
{
    const float* x     = (const float*)d_in[0];
    const float* We_ih = (const float*)d_in[1];
    const float* We_hh = (const float*)d_in[2];
    const float* be_ih = (const float*)d_in[3];
    const float* be_hh = (const float*)d_in[4];
    const float* Wd_ih = (const float*)d_in[5];
    const float* Wd_hh = (const float*)d_in[6];
    const float* bd_ih = (const float*)d_in[7];
    const float* bd_hh = (const float*)d_in[8];
    float* out = (float*)d_out;

    rnn_kernel<<<NCTA, 256>>>(x, We_ih, We_hh, be_ih, be_hh,
                              Wd_ih, Wd_hh, bd_ih, bd_hh, out);
}